// round 17
// baseline (speedup 1.0000x reference)
#include <cuda_runtime.h>
#include <math.h>

// Net_43490838839931: batched RK4 of ds/dt = MLP([s,u]) with 2->4->1 LeakyReLU net.
// R11: COALESCED STORES. Each warp owns 32 consecutive elements; per-step states
// staged to SMEM [time][lane] (stride 33, conflict-free); every 32 steps flush
// transposed so each STG.32 covers a contiguous 128B run of ONE element's
// timeline (1-2 lines vs 32 divergent lines before). Math = R7's 40-slot form:
// incremental RK4 on affine hinges, sign-specialized so sign*|g| folds into
// FADD +-|src| modifiers. 1 element/thread -> 4096 warps (6.9/SMSP).

#define NSTEPS 100
#define TPB 128
#define WPB (TPB / 32)

struct Uni {
    float R0, R1, R2, R3;      // q_j * w1a_j
    float hR0, hR1, hR2, hR3;  // 0.5 * R_j
    float P, hP;               // sum p_j*w1a_j, half of it
};

struct El {                    // per-element affine constants
    float Qt, D0, D1, D2, D3;
};

template <int SGN>
__device__ __forceinline__ float dynsum(float g0, float g1, float g2, float g3,
                                        float lin) {
    // FADD with ±|src| modifiers — abs and sign are free in SASS.
    float A0 = (SGN & 1) ? -fabsf(g0) : fabsf(g0);
    float A1 = (SGN & 2) ? -fabsf(g1) : fabsf(g1);
    float A2 = (SGN & 4) ? -fabsf(g2) : fabsf(g2);
    float A3 = (SGN & 8) ? -fabsf(g3) : fabsf(g3);
    return lin + ((A0 + A1) + (A2 + A3));
}

template <int SGN>
__device__ __forceinline__ float step1(const Uni& U, const El& e, float s) {
    // stage 1 at s
    float g0 = fmaf(s, U.R0, e.D0);
    float g1 = fmaf(s, U.R1, e.D1);
    float g2 = fmaf(s, U.R2, e.D2);
    float g3 = fmaf(s, U.R3, e.D3);
    float lin1 = fmaf(U.P, s, e.Qt);
    float k1 = dynsum<SGN>(g0, g1, g2, g3, lin1);
    // stage 2 at s + 0.5*k1 (incremental)
    float h0 = fmaf(k1, U.hR0, g0);
    float h1 = fmaf(k1, U.hR1, g1);
    float h2 = fmaf(k1, U.hR2, g2);
    float h3 = fmaf(k1, U.hR3, g3);
    float lin2 = fmaf(k1, U.hP, lin1);
    float k2 = dynsum<SGN>(h0, h1, h2, h3, lin2);
    // stage 3 at s + 0.5*k2
    float m0 = fmaf(k2, U.hR0, g0);
    float m1 = fmaf(k2, U.hR1, g1);
    float m2 = fmaf(k2, U.hR2, g2);
    float m3 = fmaf(k2, U.hR3, g3);
    float lin3 = fmaf(k2, U.hP, lin1);
    float k3 = dynsum<SGN>(m0, m1, m2, m3, lin3);
    // stage 4 at s + k3
    float n0 = fmaf(k3, U.R0, g0);
    float n1 = fmaf(k3, U.R1, g1);
    float n2 = fmaf(k3, U.R2, g2);
    float n3 = fmaf(k3, U.R3, g3);
    float lin4 = fmaf(k3, U.P, lin1);
    float k4 = dynsum<SGN>(n0, n1, n2, n3, lin4);
    // combine
    float t = k2 + k3;
    float w = k1 + k4;
    float sum = fmaf(2.0f, t, w);
    return fmaf(sum, 0.16666667f, s);
}

// Flush one 32-step window, transposed: lane l stores element e's time t0+l.
// Addresses across lanes are contiguous 4B -> 128B runs (1-2 lines per STG).
__device__ __forceinline__ void flush32(const float* wb, float* outw, int t0,
                                        int lane) {
    __syncwarp();
    #pragma unroll
    for (int e = 0; e < 32; ++e) {
        outw[e * NSTEPS + t0 + lane] = wb[lane * 33 + e];
    }
    __syncwarp();
}

template <int SGN>
__device__ __forceinline__ void run_loop(const Uni& U, const El& e, float s,
                                         float* wb, float* outw, int lane) {
    // Window 0: row 0 = initial state, rows 1..31 = steps 1..31.
    wb[0 * 33 + lane] = s;
    #pragma unroll 4
    for (int t = 1; t < 32; ++t) {
        s = step1<SGN>(U, e, s);
        wb[t * 33 + lane] = s;
    }
    flush32(wb, outw, 0, lane);

    // Windows 1,2: 32 steps each (t = 32..63, 64..95).
    #pragma unroll 1
    for (int wdw = 1; wdw < 3; ++wdw) {
        #pragma unroll 4
        for (int t = 0; t < 32; ++t) {
            s = step1<SGN>(U, e, s);
            wb[t * 33 + lane] = s;
        }
        flush32(wb, outw, wdw * 32, lane);
    }

    // Tail: 4 steps (t = 96..99), per-thread float4 (16B-aligned: 384 % 16 == 0).
    float4 v;
    s = step1<SGN>(U, e, s); v.x = s;
    s = step1<SGN>(U, e, s); v.y = s;
    s = step1<SGN>(U, e, s); v.z = s;
    s = step1<SGN>(U, e, s); v.w = s;
    *reinterpret_cast<float4*>(outw + lane * NSTEPS + 96) = v;
}

__global__ __launch_bounds__(TPB) void rk4_kernel(
    const float* __restrict__ x, const float* __restrict__ u,
    const float* __restrict__ W1, const float* __restrict__ b1,
    const float* __restrict__ W2, const float* __restrict__ b2,
    float* __restrict__ out, int B)
{
    __shared__ float buf[WPB][33 * 32];

    int tid = blockIdx.x * TPB + threadIdx.x;
    if (tid >= B) return;
    int warp = threadIdx.x / 32;
    int lane = threadIdx.x % 32;

    float xx = x[tid];          // coalesced scalar loads
    float uu = u[tid];

    // W1 [2,4] row-major: row 0 multiplies s, row 1 multiplies u.
    float a0 = W1[0], a1 = W1[1], a2 = W1[2], a3 = W1[3];
    float u0 = W1[4], u1 = W1[5], u2 = W1[6], u3 = W1[7];
    float v0 = W2[0], v1 = W2[1], v2 = W2[2], v3 = W2[3];

    float p0 = 0.505f * v0, p1 = 0.505f * v1, p2 = 0.505f * v2, p3 = 0.505f * v3;
    float q0 = 0.495f * v0, q1 = 0.495f * v1, q2 = 0.495f * v2, q3 = 0.495f * v3;
    float bb = b2[0];

    Uni U;
    U.R0 = q0 * a0; U.R1 = q1 * a1; U.R2 = q2 * a2; U.R3 = q3 * a3;
    U.hR0 = 0.5f * U.R0; U.hR1 = 0.5f * U.R1;
    U.hR2 = 0.5f * U.R2; U.hR3 = 0.5f * U.R3;
    U.P = fmaf(p0, a0, fmaf(p1, a1, fmaf(p2, a2, p3 * a3)));
    U.hP = 0.5f * U.P;

    El E;
    {
        float c0 = fmaf(uu, u0, b1[0]);
        float c1 = fmaf(uu, u1, b1[1]);
        float c2 = fmaf(uu, u2, b1[2]);
        float c3 = fmaf(uu, u3, b1[3]);
        E.Qt = bb + fmaf(p0, c0, fmaf(p1, c1, fmaf(p2, c2, p3 * c3)));
        E.D0 = q0 * c0; E.D1 = q1 * c1;
        E.D2 = q2 * c2; E.D3 = q3 * c3;
    }

    // Warp's output base: first element of this warp.
    int bBase = blockIdx.x * TPB + warp * 32;
    float* outw = out + (size_t)bBase * NSTEPS;
    float* wb = buf[warp];

    // 4-bit sign code of W2 (uniform across all threads -> no divergence).
    int code = (v0 < 0.0f ? 1 : 0) | (v1 < 0.0f ? 2 : 0) |
               (v2 < 0.0f ? 4 : 0) | (v3 < 0.0f ? 8 : 0);

    switch (code) {
        case 0:  run_loop<0 >(U, E, xx, wb, outw, lane); break;
        case 1:  run_loop<1 >(U, E, xx, wb, outw, lane); break;
        case 2:  run_loop<2 >(U, E, xx, wb, outw, lane); break;
        case 3:  run_loop<3 >(U, E, xx, wb, outw, lane); break;
        case 4:  run_loop<4 >(U, E, xx, wb, outw, lane); break;
        case 5:  run_loop<5 >(U, E, xx, wb, outw, lane); break;
        case 6:  run_loop<6 >(U, E, xx, wb, outw, lane); break;
        case 7:  run_loop<7 >(U, E, xx, wb, outw, lane); break;
        case 8:  run_loop<8 >(U, E, xx, wb, outw, lane); break;
        case 9:  run_loop<9 >(U, E, xx, wb, outw, lane); break;
        case 10: run_loop<10>(U, E, xx, wb, outw, lane); break;
        case 11: run_loop<11>(U, E, xx, wb, outw, lane); break;
        case 12: run_loop<12>(U, E, xx, wb, outw, lane); break;
        case 13: run_loop<13>(U, E, xx, wb, outw, lane); break;
        case 14: run_loop<14>(U, E, xx, wb, outw, lane); break;
        case 15: run_loop<15>(U, E, xx, wb, outw, lane); break;
    }
}

extern "C" void kernel_launch(void* const* d_in, const int* in_sizes, int n_in,
                              void* d_out, int out_size)
{
    const float* x  = (const float*)d_in[0];
    const float* u  = (const float*)d_in[1];
    const float* W1 = (const float*)d_in[2];
    const float* b1 = (const float*)d_in[3];
    const float* W2 = (const float*)d_in[4];
    const float* b2 = (const float*)d_in[5];
    float* out = (float*)d_out;
    int B = in_sizes[0];

    int blocks = (B + TPB - 1) / TPB;    // 1024 blocks of 128 -> 4096 warps
    rk4_kernel<<<blocks, TPB>>>(x, u, W1, b1, W2, b2, out, B);
}